// round 13
// baseline (speedup 1.0000x reference)
#include <cuda_runtime.h>
#include <cuda_fp16.h>
#include <cstdint>

#define NROWS   8192
#define DDIM    128
#define JSPLIT  16
#define TILES_PER_CTA 4          // 64 j-tiles / 16 splits
#define NCLS    1024
#define KMAX    64               // max class size for Smat fast path
#define KMID    256              // max class size for rows-cache path
#define LOG2E   1.44269504f

// smem tile: 128 rows x 128 fp16, padded row stride 136 fp16 = 272 B
#define TSTRIDE 272
#define TILE_BYTES (128 * TSTRIDE)   // 34816

// ---------------- device scratch (no allocations allowed) ----------------
__device__ __half g_af[NROWS * DDIM];
__device__ __half g_bf[NROWS * DDIM];
__device__ float g_vpart[JSPLIT * NROWS];   // unconditional row sums (partials)
__device__ float g_csum[NCLS];
__device__ int   g_ccnt[NCLS];
__device__ unsigned g_done = 0;             // wraps to 0 every replay (atomicInc)

// ---------------- helpers ----------------
static __device__ __forceinline__ uint32_t smem_u32(const void* p) {
    uint32_t a;
    asm("{ .reg .u64 t; cvta.to.shared.u64 t, %1; cvt.u32.u64 %0, t; }" : "=r"(a) : "l"(p));
    return a;
}
static __device__ __forceinline__ void cp16(uint32_t dst, const void* src) {
    asm volatile("cp.async.cg.shared.global [%0], [%1], 16;" :: "r"(dst), "l"(src));
}
#define CP_COMMIT()  asm volatile("cp.async.commit_group;" ::: "memory")
#define CP_WAIT0()   asm volatile("cp.async.wait_group 0;" ::: "memory")

static __device__ __forceinline__ void ldsm4(uint32_t& r0, uint32_t& r1,
                                             uint32_t& r2, uint32_t& r3, uint32_t addr) {
    asm volatile("ldmatrix.sync.aligned.m8n8.x4.shared.b16 {%0,%1,%2,%3}, [%4];"
                 : "=r"(r0), "=r"(r1), "=r"(r2), "=r"(r3) : "r"(addr));
}
// fp16-accumulate HMMA: d0 = half2(cols c0,c1)@row r, d1 = half2@row r+8
static __device__ __forceinline__ void mma16816_f16(uint32_t& d0, uint32_t& d1,
        uint32_t a0, uint32_t a1, uint32_t a2, uint32_t a3, uint32_t b0, uint32_t b1) {
    asm volatile(
        "mma.sync.aligned.m16n8k16.row.col.f16.f16.f16.f16 "
        "{%0,%1}, {%2,%3,%4,%5}, {%6,%7}, {%0,%1};"
        : "+r"(d0), "+r"(d1)
        : "r"(a0), "r"(a1), "r"(a2), "r"(a3), "r"(b0), "r"(b1));
}
static __device__ __forceinline__ float exp1p(float s) {   // exp(1 + s), f32
    return exp2f(fmaf(s, LOG2E, LOG2E));
}
// sum of exp(1+s) over a half2 of s: 1 HADD2 + 1 f16x2 MUFU
static __device__ __forceinline__ float expsum_h2(uint32_t h2bits) {
    const __half2 one2 = __floats2half2_rn(1.0f, 1.0f);
    __half2 h = __hadd2(*reinterpret_cast<__half2*>(&h2bits), one2);
    float2 e = __half22float2(h2exp(h));
    return e.x + e.y;
}

// ---------------- conversion: fp32 -> fp16 (inputs are unit-norm rows) ----------------
__global__ void __launch_bounds__(256)
convert_kernel(const float* __restrict__ a, const float* __restrict__ b) {
    int i = (blockIdx.x * 256 + threadIdx.x) * 4;
    float4 va = *reinterpret_cast<const float4*>(a + i);
    float4 vb = *reinterpret_cast<const float4*>(b + i);
    __half2* pa = reinterpret_cast<__half2*>(g_af + i);
    __half2* pb = reinterpret_cast<__half2*>(g_bf + i);
    pa[0] = __floats2half2_rn(va.x, va.y);
    pa[1] = __floats2half2_rn(va.z, va.w);
    pb[0] = __floats2half2_rn(vb.x, vb.y);
    pb[1] = __floats2half2_rn(vb.z, vb.w);
}

// issue cp.async for a 128x128 fp16 tile (8 x 16B per thread)
static __device__ __forceinline__ void tile_cp_async(uint32_t dst_base,
        const __half* __restrict__ src, int rowBase) {
    const int t = threadIdx.x;
    #pragma unroll
    for (int it = 0; it < 8; it++) {
        int g = t + it * 256;        // 0..2047
        int r = g >> 4;
        int c = g & 15;              // 16B chunk within row
        cp16(dst_base + (uint32_t)(r * TSTRIDE + c * 16),
             src + (size_t)(rowBase + r) * DDIM + c * 8);
    }
}

// ---------------- pass 1: HMMA (f16 acc) GEMM + fused exp row-sums ----------------
extern __shared__ char smem_raw[];

__global__ void __launch_bounds__(256, 1)
pass1_mma() {
    char* As = smem_raw;
    char* Bs0 = smem_raw + TILE_BYTES;
    char* Bs1 = smem_raw + 2 * TILE_BYTES;

    __shared__ float vred[128][2];

    const int tid  = threadIdx.x;
    const int wid  = tid >> 5;
    const int lane = tid & 31;
    const int wm   = wid >> 1;          // 0..3  (rows: wm*32)
    const int wn   = wid & 1;           // 0..1  (cols: wn*64)
    const int rowBase = blockIdx.x * 128;
    const int jt0     = blockIdx.y * TILES_PER_CTA;

    const uint32_t asu = smem_u32(As);
    const uint32_t bsu[2] = { smem_u32(Bs0), smem_u32(Bs1) };

    // prologue: A tile + B tile 0
    tile_cp_async(asu, g_af, rowBase);
    tile_cp_async(bsu[0], g_bf, jt0 * 128);
    CP_COMMIT();
    CP_WAIT0();
    __syncthreads();

    // per-lane ldmatrix base addresses
    const uint32_t aoff = (uint32_t)((wm * 32 + (lane & 15)) * TSTRIDE + ((lane >> 4) << 4));
    const uint32_t boff = (uint32_t)((wn * 64 + (lane & 7) + ((lane >> 4) << 3)) * TSTRIDE
                                     + (((lane >> 3) & 1) << 4));

    // hoist A fragments: tile-invariant (64 regs)
    uint32_t aF[8][2][4];
    #pragma unroll
    for (int ks = 0; ks < 8; ks++)
        #pragma unroll
        for (int mf = 0; mf < 2; mf++)
            ldsm4(aF[ks][mf][0], aF[ks][mf][1], aF[ks][mf][2], aF[ks][mf][3],
                  asu + aoff + (uint32_t)(mf * 16 * TSTRIDE + ks * 32));

    const int r0 = wm * 32 + (lane >> 2);
    float vr00 = 0.f, vr01 = 0.f, vr10 = 0.f, vr11 = 0.f;

    for (int t = 0; t < TILES_PER_CTA; t++) {
        const int cb = t & 1, nb = (t + 1) & 1;
        if (t + 1 < TILES_PER_CTA) {
            tile_cp_async(bsu[nb], g_bf, (jt0 + t + 1) * 128);
            CP_COMMIT();
        }

        // f16x2 accumulators: acc[mf][nf][0]=row r, [1]=row r+8 (cols pair)
        uint32_t acc[2][8][2];
        #pragma unroll
        for (int mf = 0; mf < 2; mf++)
            #pragma unroll
            for (int nf = 0; nf < 8; nf++) { acc[mf][nf][0] = 0u; acc[mf][nf][1] = 0u; }

        const uint32_t bbase = bsu[cb] + boff;

        // double-buffered B fragments across k-steps
        uint32_t bF[2][8][2];
        #pragma unroll
        for (int np = 0; np < 4; np++) {
            uint32_t q0, q1, q2, q3;
            ldsm4(q0, q1, q2, q3, bbase + (uint32_t)(np * 16 * TSTRIDE));
            bF[0][np * 2 + 0][0] = q0; bF[0][np * 2 + 0][1] = q1;
            bF[0][np * 2 + 1][0] = q2; bF[0][np * 2 + 1][1] = q3;
        }

        #pragma unroll
        for (int ks = 0; ks < 8; ks++) {
            const int cur = ks & 1, nxt = cur ^ 1;
            if (ks < 7) {
                const uint32_t kb = (uint32_t)((ks + 1) * 32);
                #pragma unroll
                for (int np = 0; np < 4; np++) {
                    uint32_t q0, q1, q2, q3;
                    ldsm4(q0, q1, q2, q3, bbase + (uint32_t)(np * 16 * TSTRIDE) + kb);
                    bF[nxt][np * 2 + 0][0] = q0; bF[nxt][np * 2 + 0][1] = q1;
                    bF[nxt][np * 2 + 1][0] = q2; bF[nxt][np * 2 + 1][1] = q3;
                }
            }
            #pragma unroll
            for (int mf = 0; mf < 2; mf++)
                #pragma unroll
                for (int nf = 0; nf < 8; nf++)
                    mma16816_f16(acc[mf][nf][0], acc[mf][nf][1],
                                 aF[ks][mf][0], aF[ks][mf][1], aF[ks][mf][2], aF[ks][mf][3],
                                 bF[cur][nf][0], bF[cur][nf][1]);
        }

        // epilogue: exp row-sums — 1 MUFU (f16x2 ex2) per 2 elements, no CVTs
        #pragma unroll
        for (int nf = 0; nf < 8; nf++) {
            vr00 += expsum_h2(acc[0][nf][0]);
            vr01 += expsum_h2(acc[0][nf][1]);
            vr10 += expsum_h2(acc[1][nf][0]);
            vr11 += expsum_h2(acc[1][nf][1]);
        }

        if (t + 1 < TILES_PER_CTA) CP_WAIT0();
        __syncthreads();
    }

    // deterministic reduction: quad shuffle -> vred -> 2-way sum
    #pragma unroll
    for (int off = 1; off <= 2; off <<= 1) {
        vr00 += __shfl_xor_sync(0xffffffffu, vr00, off);
        vr01 += __shfl_xor_sync(0xffffffffu, vr01, off);
        vr10 += __shfl_xor_sync(0xffffffffu, vr10, off);
        vr11 += __shfl_xor_sync(0xffffffffu, vr11, off);
    }
    if ((lane & 3) == 0) {
        vred[r0     ][wn] = vr00;
        vred[r0 +  8][wn] = vr01;
        vred[r0 + 16][wn] = vr10;
        vred[r0 + 24][wn] = vr11;
    }
    __syncthreads();
    if (tid < 128)
        g_vpart[blockIdx.y * NROWS + rowBase + tid] = vred[tid][0] + vred[tid][1];
}

// ---------------- pass 2: per class — compaction + V corr + hinge + fused finalize ----------------
__global__ void __launch_bounds__(256)
pass2_all(const float* __restrict__ a, const float* __restrict__ b,
          const int* __restrict__ labels, float* __restrict__ out) {
    __shared__ float Smat[KMAX * KMAX];   // 16 KB (reused as finalize scratch)
    __shared__ float Vs[KMID];
    __shared__ int   rows[KMID];
    __shared__ float wsum[8];
    __shared__ int   wpop[8], wbase[8];
    __shared__ int   s_k;
    __shared__ unsigned s_ticket;

    const int c = blockIdx.x;
    const int tid = threadIdx.x;
    const int warp = tid >> 5, lane = tid & 31;

    if (tid == 0) s_k = 0;
    __syncthreads();

    // deterministic class compaction: 8 chunks of 1024 labels, index order
    #pragma unroll 1
    for (int ch = 0; ch < 8; ch++) {
        const int base_row = ch * 1024 + tid * 4;
        const int4 l4 = *reinterpret_cast<const int4*>(&labels[base_row]);
        unsigned m = (l4.x == c ? 1u : 0u) | (l4.y == c ? 2u : 0u)
                   | (l4.z == c ? 4u : 0u) | (l4.w == c ? 8u : 0u);
        int pc = __popc(m);
        int inc = pc;
        #pragma unroll
        for (int off = 1; off < 32; off <<= 1) {
            int v = __shfl_up_sync(0xffffffffu, inc, off);
            if (lane >= off) inc += v;
        }
        if (lane == 31) wpop[warp] = inc;
        __syncthreads();
        if (tid == 0) {
            int run = s_k;
            #pragma unroll
            for (int w = 0; w < 8; w++) { wbase[w] = run; run += wpop[w]; }
            s_k = run;
        }
        __syncthreads();
        int idx = wbase[warp] + inc - pc;
        if (m & 1) { if (idx < KMID) rows[idx] = base_row;     idx++; }
        if (m & 2) { if (idx < KMID) rows[idx] = base_row + 1; idx++; }
        if (m & 4) { if (idx < KMID) rows[idx] = base_row + 2; idx++; }
        if (m & 8) { if (idx < KMID) rows[idx] = base_row + 3; idx++; }
    }
    __syncthreads();
    const int k = min(s_k, KMID);

    if (k <= 1) {
        if (tid == 0) { g_csum[c] = 0.f; g_ccnt[c] = 0; }
    } else if (k <= KMAX) {
        // phase A: all k*k exact dots into Smat
        for (int p = warp; p < k * k; p += 8) {
            const int x = p / k, y = p - x * k;
            const float4 af = *reinterpret_cast<const float4*>(
                &a[(size_t)rows[x] * DDIM + lane * 4]);
            const float4 bf = *reinterpret_cast<const float4*>(
                &b[(size_t)rows[y] * DDIM + lane * 4]);
            float d = af.x * bf.x + af.y * bf.y + af.z * bf.z + af.w * bf.w;
            #pragma unroll
            for (int o = 16; o; o >>= 1) d += __shfl_xor_sync(0xffffffffu, d, o);
            if (lane == 0) Smat[x * KMAX + y] = d;
        }
        __syncthreads();

        // V[x] = R[x] (pass1 partials) - sum over class (incl self) of exp(1+S)
        if (tid < k) {
            const int i = rows[tid];
            float v0 = 0.f;
            #pragma unroll
            for (int s = 0; s < JSPLIT; s++) v0 += g_vpart[s * NROWS + i];
            float corr = 0.f;
            for (int y = 0; y < k; y++) corr += exp1p(Smat[tid * KMAX + y]);
            Vs[tid] = v0 - corr;
        }
        __syncthreads();

        // phase B: hinge over ordered pairs x != y
        float hs = 0.f;
        for (int p = tid; p < k * k; p += 256) {
            const int x = p / k, y = p - x * k;
            if (x == y) continue;
            const float h = fmaxf(logf(Vs[x] + Vs[y]) - Smat[x * KMAX + y], 0.f);
            hs += h * h;
        }
        #pragma unroll
        for (int o = 16; o; o >>= 1) hs += __shfl_xor_sync(0xffffffffu, hs, o);
        if (lane == 0) wsum[warp] = hs;
        __syncthreads();
        if (tid == 0) {
            float s = 0.f;
            #pragma unroll
            for (int w = 0; w < 8; w++) s += wsum[w];
            g_csum[c] = s;
            g_ccnt[c] = k * (k - 1);
        }
    } else {
        // mid path 64 < k <= 256 (statistically unreachable for Poisson(8))
        for (int x = warp; x < k; x += 8) {
            const int i = rows[x];
            const float4 af = *reinterpret_cast<const float4*>(
                &a[(size_t)i * DDIM + lane * 4]);
            float corr = 0.f;
            for (int y = 0; y < k; y++) {
                const float4 bf = *reinterpret_cast<const float4*>(
                    &b[(size_t)rows[y] * DDIM + lane * 4]);
                float d = af.x * bf.x + af.y * bf.y + af.z * bf.z + af.w * bf.w;
                #pragma unroll
                for (int o = 16; o; o >>= 1) d += __shfl_xor_sync(0xffffffffu, d, o);
                corr += exp1p(d);
            }
            float v0 = 0.f;
            #pragma unroll
            for (int s = 0; s < JSPLIT; s++) v0 += g_vpart[s * NROWS + i];
            if (lane == 0) Vs[x] = v0 - corr;
        }
        __syncthreads();
        float hs = 0.f;
        for (int p = warp; p < k * k; p += 8) {
            const int x = p / k, y = p - x * k;
            if (x == y) continue;
            const float4 af = *reinterpret_cast<const float4*>(
                &a[(size_t)rows[x] * DDIM + lane * 4]);
            const float4 bf = *reinterpret_cast<const float4*>(
                &b[(size_t)rows[y] * DDIM + lane * 4]);
            float d = af.x * bf.x + af.y * bf.y + af.z * bf.z + af.w * bf.w;
            #pragma unroll
            for (int o = 16; o; o >>= 1) d += __shfl_xor_sync(0xffffffffu, d, o);
            if (lane == 0) {
                const float h = fmaxf(logf(Vs[x] + Vs[y]) - d, 0.f);
                hs += h * h;
            }
        }
        if (lane == 0) wsum[warp] = hs;
        __syncthreads();
        if (tid == 0) {
            float s = 0.f;
            #pragma unroll
            for (int w = 0; w < 8; w++) s += wsum[w];
            g_csum[c] = s;
            g_ccnt[c] = k * (k - 1);
        }
    }

    // fused finalize: last block (ticket wraps to 0 every replay -> graph-safe)
    if (tid == 0) {
        __threadfence();
        s_ticket = atomicInc(&g_done, NCLS - 1);
    }
    __syncthreads();
    if (s_ticket == NCLS - 1) {
        float* sh = Smat;                                    // reuse smem
        int*   sc = reinterpret_cast<int*>(Smat + 256);
        float s = 0.f;
        int   n = 0;
        #pragma unroll
        for (int i = tid; i < NCLS; i += 256) { s += g_csum[i]; n += g_ccnt[i]; }
        sh[tid] = s;
        sc[tid] = n;
        __syncthreads();
        for (int o = 128; o; o >>= 1) {
            if (tid < o) { sh[tid] += sh[tid + o]; sc[tid] += sc[tid + o]; }
            __syncthreads();
        }
        if (tid == 0) out[0] = sh[0] / (2.0f * (float)sc[0]);
    }
}

// ---------------- launch ----------------
extern "C" void kernel_launch(void* const* d_in, const int* in_sizes, int n_in,
                              void* d_out, int out_size) {
    const float* a      = (const float*)d_in[0];
    const float* b      = (const float*)d_in[1];
    const int*   labels = (const int*)d_in[2];
    float*       out    = (float*)d_out;

    const int smemBytes = 3 * TILE_BYTES;   // 104448: A + double-buffered B
    cudaFuncSetAttribute(pass1_mma, cudaFuncAttributeMaxDynamicSharedMemorySize, smemBytes);

    convert_kernel<<<NROWS * DDIM / 1024, 256>>>(a, b);
    dim3 g1(NROWS / 128, JSPLIT);           // (64, 16) = 1024 CTAs
    pass1_mma<<<g1, 256, smemBytes>>>();
    pass2_all<<<NCLS, 256>>>(a, b, labels, out);
}

// round 16
// speedup vs baseline: 1.1188x; 1.1188x over previous
#include <cuda_runtime.h>
#include <cuda_fp16.h>
#include <cstdint>

#define NROWS   8192
#define DDIM    128
#define JSPLIT  16
#define TILES_PER_CTA 4          // 64 j-tiles / 16 splits
#define NCLS    1024
#define KMAX    64               // max class size for Smat fast path
#define KMID    256              // max class size for rows-cache path
#define LOG2E   1.44269504f
#define E_CONST 2.71828182845904523536f

// smem tile: 128 rows x 128 fp16, padded row stride 136 fp16 = 272 B
#define TSTRIDE 272
#define TILE_BYTES (128 * TSTRIDE)   // 34816

// ---------------- device scratch (no allocations allowed) ----------------
__device__ __half g_af[NROWS * DDIM];       // a * log2(e), fp16
__device__ __half g_bf[NROWS * DDIM];       // b, fp16
__device__ float g_vpart[JSPLIT * NROWS];   // partials of sum_j exp2(S*log2e)  (no e factor)
__device__ float g_csum[NCLS];
__device__ int   g_ccnt[NCLS];
__device__ unsigned g_done = 0;             // wraps to 0 every replay (atomicInc)

// ---------------- helpers ----------------
static __device__ __forceinline__ uint32_t smem_u32(const void* p) {
    uint32_t a;
    asm("{ .reg .u64 t; cvta.to.shared.u64 t, %1; cvt.u32.u64 %0, t; }" : "=r"(a) : "l"(p));
    return a;
}
static __device__ __forceinline__ void cp16(uint32_t dst, const void* src) {
    asm volatile("cp.async.cg.shared.global [%0], [%1], 16;" :: "r"(dst), "l"(src));
}
#define CP_COMMIT()  asm volatile("cp.async.commit_group;" ::: "memory")
#define CP_WAIT0()   asm volatile("cp.async.wait_group 0;" ::: "memory")

static __device__ __forceinline__ void ldsm4(uint32_t& r0, uint32_t& r1,
                                             uint32_t& r2, uint32_t& r3, uint32_t addr) {
    asm volatile("ldmatrix.sync.aligned.m8n8.x4.shared.b16 {%0,%1,%2,%3}, [%4];"
                 : "=r"(r0), "=r"(r1), "=r"(r2), "=r"(r3) : "r"(addr));
}
static __device__ __forceinline__ void mma16816(float& d0, float& d1, float& d2, float& d3,
        uint32_t a0, uint32_t a1, uint32_t a2, uint32_t a3, uint32_t b0, uint32_t b1) {
    asm volatile(
        "mma.sync.aligned.m16n8k16.row.col.f32.f16.f16.f32 "
        "{%0,%1,%2,%3}, {%4,%5,%6,%7}, {%8,%9}, {%0,%1,%2,%3};"
        : "+f"(d0), "+f"(d1), "+f"(d2), "+f"(d3)
        : "r"(a0), "r"(a1), "r"(a2), "r"(a3), "r"(b0), "r"(b1));
}
static __device__ __forceinline__ float exp1p(float s) {   // exp(1 + s), f32
    return exp2f(fmaf(s, LOG2E, LOG2E));
}

// ---------------- conversion: fp32 -> fp16; a is pre-scaled by log2(e) ----------------
__global__ void __launch_bounds__(256)
convert_kernel(const float* __restrict__ a, const float* __restrict__ b) {
    int i = (blockIdx.x * 256 + threadIdx.x) * 4;
    float4 va = *reinterpret_cast<const float4*>(a + i);
    float4 vb = *reinterpret_cast<const float4*>(b + i);
    __half2* pa = reinterpret_cast<__half2*>(g_af + i);
    __half2* pb = reinterpret_cast<__half2*>(g_bf + i);
    pa[0] = __floats2half2_rn(va.x * LOG2E, va.y * LOG2E);
    pa[1] = __floats2half2_rn(va.z * LOG2E, va.w * LOG2E);
    pb[0] = __floats2half2_rn(vb.x, vb.y);
    pb[1] = __floats2half2_rn(vb.z, vb.w);
}

// issue cp.async for a 128x128 fp16 tile (8 x 16B per thread)
static __device__ __forceinline__ void tile_cp_async(uint32_t dst_base,
        const __half* __restrict__ src, int rowBase) {
    const int t = threadIdx.x;
    #pragma unroll
    for (int it = 0; it < 8; it++) {
        int g = t + it * 256;        // 0..2047
        int r = g >> 4;
        int c = g & 15;              // 16B chunk within row
        cp16(dst_base + (uint32_t)(r * TSTRIDE + c * 16),
             src + (size_t)(rowBase + r) * DDIM + c * 8);
    }
}

// ---------------- pass 1: HMMA GEMM (acc = S*log2e) + fused exp2 row-sums ----------------
extern __shared__ char smem_raw[];

__global__ void __launch_bounds__(256, 1)
pass1_mma() {
    char* As = smem_raw;
    char* Bs0 = smem_raw + TILE_BYTES;
    char* Bs1 = smem_raw + 2 * TILE_BYTES;

    __shared__ float vred[128][2];

    const int tid  = threadIdx.x;
    const int wid  = tid >> 5;
    const int lane = tid & 31;
    const int wm   = wid >> 1;          // 0..3  (rows: wm*32)
    const int wn   = wid & 1;           // 0..1  (cols: wn*64)
    const int rowBase = blockIdx.x * 128;
    const int jt0     = blockIdx.y * TILES_PER_CTA;

    const uint32_t asu = smem_u32(As);
    const uint32_t bsu[2] = { smem_u32(Bs0), smem_u32(Bs1) };

    // prologue: A tile + B tile 0
    tile_cp_async(asu, g_af, rowBase);
    tile_cp_async(bsu[0], g_bf, jt0 * 128);
    CP_COMMIT();
    CP_WAIT0();
    __syncthreads();

    // per-lane ldmatrix base addresses
    const uint32_t aoff = (uint32_t)((wm * 32 + (lane & 15)) * TSTRIDE + ((lane >> 4) << 4));
    const uint32_t boff = (uint32_t)((wn * 64 + (lane & 7) + ((lane >> 4) << 3)) * TSTRIDE
                                     + (((lane >> 3) & 1) << 4));

    // hoist A fragments: tile-invariant (64 regs)
    uint32_t aF[8][2][4];
    #pragma unroll
    for (int ks = 0; ks < 8; ks++)
        #pragma unroll
        for (int mf = 0; mf < 2; mf++)
            ldsm4(aF[ks][mf][0], aF[ks][mf][1], aF[ks][mf][2], aF[ks][mf][3],
                  asu + aoff + (uint32_t)(mf * 16 * TSTRIDE + ks * 32));

    const int r0 = wm * 32 + (lane >> 2);
    float vr00 = 0.f, vr01 = 0.f, vr10 = 0.f, vr11 = 0.f;

    for (int t = 0; t < TILES_PER_CTA; t++) {
        const int cb = t & 1, nb = (t + 1) & 1;
        if (t + 1 < TILES_PER_CTA) {
            tile_cp_async(bsu[nb], g_bf, (jt0 + t + 1) * 128);
            CP_COMMIT();
        }

        float acc[2][8][4];
        #pragma unroll
        for (int mf = 0; mf < 2; mf++)
            #pragma unroll
            for (int nf = 0; nf < 8; nf++)
                #pragma unroll
                for (int c = 0; c < 4; c++) acc[mf][nf][c] = 0.f;

        const uint32_t bbase = bsu[cb] + boff;

        // double-buffered B fragments across k-steps
        uint32_t bF[2][8][2];
        #pragma unroll
        for (int np = 0; np < 4; np++) {
            uint32_t q0, q1, q2, q3;
            ldsm4(q0, q1, q2, q3, bbase + (uint32_t)(np * 16 * TSTRIDE));
            bF[0][np * 2 + 0][0] = q0; bF[0][np * 2 + 0][1] = q1;
            bF[0][np * 2 + 1][0] = q2; bF[0][np * 2 + 1][1] = q3;
        }

        #pragma unroll
        for (int ks = 0; ks < 8; ks++) {
            const int cur = ks & 1, nxt = cur ^ 1;
            if (ks < 7) {
                const uint32_t kb = (uint32_t)((ks + 1) * 32);
                #pragma unroll
                for (int np = 0; np < 4; np++) {
                    uint32_t q0, q1, q2, q3;
                    ldsm4(q0, q1, q2, q3, bbase + (uint32_t)(np * 16 * TSTRIDE) + kb);
                    bF[nxt][np * 2 + 0][0] = q0; bF[nxt][np * 2 + 0][1] = q1;
                    bF[nxt][np * 2 + 1][0] = q2; bF[nxt][np * 2 + 1][1] = q3;
                }
            }
            #pragma unroll
            for (int mf = 0; mf < 2; mf++)
                #pragma unroll
                for (int nf = 0; nf < 8; nf++)
                    mma16816(acc[mf][nf][0], acc[mf][nf][1], acc[mf][nf][2], acc[mf][nf][3],
                             aF[ks][mf][0], aF[ks][mf][1], aF[ks][mf][2], aF[ks][mf][3],
                             bF[cur][nf][0], bF[cur][nf][1]);
        }

        // epilogue: acc already = S*log2e -> one MUFU.EX2 + one FADD per element
        #pragma unroll
        for (int nf = 0; nf < 8; nf++) {
            vr00 += exp2f(acc[0][nf][0]) + exp2f(acc[0][nf][1]);
            vr01 += exp2f(acc[0][nf][2]) + exp2f(acc[0][nf][3]);
            vr10 += exp2f(acc[1][nf][0]) + exp2f(acc[1][nf][1]);
            vr11 += exp2f(acc[1][nf][2]) + exp2f(acc[1][nf][3]);
        }

        if (t + 1 < TILES_PER_CTA) CP_WAIT0();
        __syncthreads();
    }

    // deterministic reduction: quad shuffle -> vred -> 2-way sum
    #pragma unroll
    for (int off = 1; off <= 2; off <<= 1) {
        vr00 += __shfl_xor_sync(0xffffffffu, vr00, off);
        vr01 += __shfl_xor_sync(0xffffffffu, vr01, off);
        vr10 += __shfl_xor_sync(0xffffffffu, vr10, off);
        vr11 += __shfl_xor_sync(0xffffffffu, vr11, off);
    }
    if ((lane & 3) == 0) {
        vred[r0     ][wn] = vr00;
        vred[r0 +  8][wn] = vr01;
        vred[r0 + 16][wn] = vr10;
        vred[r0 + 24][wn] = vr11;
    }
    __syncthreads();
    if (tid < 128)
        g_vpart[blockIdx.y * NROWS + rowBase + tid] = vred[tid][0] + vred[tid][1];
}

// ---------------- pass 2: per class — compaction + V corr + hinge + fused finalize ----------------
__global__ void __launch_bounds__(256)
pass2_all(const float* __restrict__ a, const float* __restrict__ b,
          const int* __restrict__ labels, float* __restrict__ out) {
    __shared__ float Smat[KMAX * KMAX];   // 16 KB (reused as finalize scratch)
    __shared__ float Vs[KMID];
    __shared__ int   rows[KMID];
    __shared__ float wsum[8];
    __shared__ int   wpop[8], wbase[8];
    __shared__ int   s_k;
    __shared__ unsigned s_ticket;

    const int c = blockIdx.x;
    const int tid = threadIdx.x;
    const int warp = tid >> 5, lane = tid & 31;

    if (tid == 0) s_k = 0;
    __syncthreads();

    // deterministic class compaction: 8 chunks of 1024 labels, index order
    #pragma unroll 1
    for (int ch = 0; ch < 8; ch++) {
        const int base_row = ch * 1024 + tid * 4;
        const int4 l4 = *reinterpret_cast<const int4*>(&labels[base_row]);
        unsigned m = (l4.x == c ? 1u : 0u) | (l4.y == c ? 2u : 0u)
                   | (l4.z == c ? 4u : 0u) | (l4.w == c ? 8u : 0u);
        int pc = __popc(m);
        int inc = pc;
        #pragma unroll
        for (int off = 1; off < 32; off <<= 1) {
            int v = __shfl_up_sync(0xffffffffu, inc, off);
            if (lane >= off) inc += v;
        }
        if (lane == 31) wpop[warp] = inc;
        __syncthreads();
        if (tid == 0) {
            int run = s_k;
            #pragma unroll
            for (int w = 0; w < 8; w++) { wbase[w] = run; run += wpop[w]; }
            s_k = run;
        }
        __syncthreads();
        int idx = wbase[warp] + inc - pc;
        if (m & 1) { if (idx < KMID) rows[idx] = base_row;     idx++; }
        if (m & 2) { if (idx < KMID) rows[idx] = base_row + 1; idx++; }
        if (m & 4) { if (idx < KMID) rows[idx] = base_row + 2; idx++; }
        if (m & 8) { if (idx < KMID) rows[idx] = base_row + 3; idx++; }
    }
    __syncthreads();
    const int k = min(s_k, KMID);

    if (k <= 1) {
        if (tid == 0) { g_csum[c] = 0.f; g_ccnt[c] = 0; }
    } else if (k <= KMAX) {
        // phase A: all k*k exact dots into Smat
        for (int p = warp; p < k * k; p += 8) {
            const int x = p / k, y = p - x * k;
            const float4 af = *reinterpret_cast<const float4*>(
                &a[(size_t)rows[x] * DDIM + lane * 4]);
            const float4 bf = *reinterpret_cast<const float4*>(
                &b[(size_t)rows[y] * DDIM + lane * 4]);
            float d = af.x * bf.x + af.y * bf.y + af.z * bf.z + af.w * bf.w;
            #pragma unroll
            for (int o = 16; o; o >>= 1) d += __shfl_xor_sync(0xffffffffu, d, o);
            if (lane == 0) Smat[x * KMAX + y] = d;
        }
        __syncthreads();

        // V[x] = e * R[x] (pass1 partials, no e factor) - class corr (incl self)
        if (tid < k) {
            const int i = rows[tid];
            float v0 = 0.f;
            #pragma unroll
            for (int s = 0; s < JSPLIT; s++) v0 += g_vpart[s * NROWS + i];
            v0 *= E_CONST;
            float corr = 0.f;
            for (int y = 0; y < k; y++) corr += exp1p(Smat[tid * KMAX + y]);
            Vs[tid] = v0 - corr;
        }
        __syncthreads();

        // phase B: hinge over ordered pairs x != y
        float hs = 0.f;
        for (int p = tid; p < k * k; p += 256) {
            const int x = p / k, y = p - x * k;
            if (x == y) continue;
            const float h = fmaxf(logf(Vs[x] + Vs[y]) - Smat[x * KMAX + y], 0.f);
            hs += h * h;
        }
        #pragma unroll
        for (int o = 16; o; o >>= 1) hs += __shfl_xor_sync(0xffffffffu, hs, o);
        if (lane == 0) wsum[warp] = hs;
        __syncthreads();
        if (tid == 0) {
            float s = 0.f;
            #pragma unroll
            for (int w = 0; w < 8; w++) s += wsum[w];
            g_csum[c] = s;
            g_ccnt[c] = k * (k - 1);
        }
    } else {
        // mid path 64 < k <= 256 (statistically unreachable for Poisson(8))
        for (int x = warp; x < k; x += 8) {
            const int i = rows[x];
            const float4 af = *reinterpret_cast<const float4*>(
                &a[(size_t)i * DDIM + lane * 4]);
            float corr = 0.f;
            for (int y = 0; y < k; y++) {
                const float4 bf = *reinterpret_cast<const float4*>(
                    &b[(size_t)rows[y] * DDIM + lane * 4]);
                float d = af.x * bf.x + af.y * bf.y + af.z * bf.z + af.w * bf.w;
                #pragma unroll
                for (int o = 16; o; o >>= 1) d += __shfl_xor_sync(0xffffffffu, d, o);
                corr += exp1p(d);
            }
            float v0 = 0.f;
            #pragma unroll
            for (int s = 0; s < JSPLIT; s++) v0 += g_vpart[s * NROWS + i];
            if (lane == 0) Vs[x] = v0 * E_CONST - corr;
        }
        __syncthreads();
        float hs = 0.f;
        for (int p = warp; p < k * k; p += 8) {
            const int x = p / k, y = p - x * k;
            if (x == y) continue;
            const float4 af = *reinterpret_cast<const float4*>(
                &a[(size_t)rows[x] * DDIM + lane * 4]);
            const float4 bf = *reinterpret_cast<const float4*>(
                &b[(size_t)rows[y] * DDIM + lane * 4]);
            float d = af.x * bf.x + af.y * bf.y + af.z * bf.z + af.w * bf.w;
            #pragma unroll
            for (int o = 16; o; o >>= 1) d += __shfl_xor_sync(0xffffffffu, d, o);
            if (lane == 0) {
                const float h = fmaxf(logf(Vs[x] + Vs[y]) - d, 0.f);
                hs += h * h;
            }
        }
        if (lane == 0) wsum[warp] = hs;
        __syncthreads();
        if (tid == 0) {
            float s = 0.f;
            #pragma unroll
            for (int w = 0; w < 8; w++) s += wsum[w];
            g_csum[c] = s;
            g_ccnt[c] = k * (k - 1);
        }
    }

    // fused finalize: last block (ticket wraps to 0 every replay -> graph-safe)
    if (tid == 0) {
        __threadfence();
        s_ticket = atomicInc(&g_done, NCLS - 1);
    }
    __syncthreads();
    if (s_ticket == NCLS - 1) {
        float* sh = Smat;                                    // reuse smem
        int*   sc = reinterpret_cast<int*>(Smat + 256);
        float s = 0.f;
        int   n = 0;
        #pragma unroll
        for (int i = tid; i < NCLS; i += 256) { s += g_csum[i]; n += g_ccnt[i]; }
        sh[tid] = s;
        sc[tid] = n;
        __syncthreads();
        for (int o = 128; o; o >>= 1) {
            if (tid < o) { sh[tid] += sh[tid + o]; sc[tid] += sc[tid + o]; }
            __syncthreads();
        }
        if (tid == 0) out[0] = sh[0] / (2.0f * (float)sc[0]);
    }
}

// ---------------- launch ----------------
extern "C" void kernel_launch(void* const* d_in, const int* in_sizes, int n_in,
                              void* d_out, int out_size) {
    const float* a      = (const float*)d_in[0];
    const float* b      = (const float*)d_in[1];
    const int*   labels = (const int*)d_in[2];
    float*       out    = (float*)d_out;

    const int smemBytes = 3 * TILE_BYTES;   // 104448: A + double-buffered B
    cudaFuncSetAttribute(pass1_mma, cudaFuncAttributeMaxDynamicSharedMemorySize, smemBytes);

    convert_kernel<<<NROWS * DDIM / 1024, 256>>>(a, b);
    dim3 g1(NROWS / 128, JSPLIT);           // (64, 16) = 1024 CTAs
    pass1_mma<<<g1, 256, smemBytes>>>();
    pass2_all<<<NCLS, 256>>>(a, b, labels, out);
}